// round 4
// baseline (speedup 1.0000x reference)
#include <cuda_runtime.h>
#include <math.h>

// ---------------------------------------------------------------------------
// Problem constants (V=2, L=2, NP=NC=120000, D=128, S=100, NNEG=50, TEMP=0.5)
// ---------------------------------------------------------------------------
#define DD     128
#define SS     100
#define NNEGC  50
#define NNODE  120000
#define RPB    64            // rows per projection block
#define N_ANCHOR 3200
#define N_ROWS   43200
#define N_SAMPLES 800
#define TEMP_INV 2.0f
#define WT_STRIDE 134        // transposed-W row stride (floats): even => 8B-aligned b64

// Scratch (device globals: no runtime allocation allowed)
__device__ float g_proj[(size_t)N_ROWS * DD];   // ~22.1 MB
__device__ float g_loss[N_SAMPLES];
__device__ int   g_is64;

// ---------------------------------------------------------------------------
// Packed f32x2 helpers (sm_100+)
// ---------------------------------------------------------------------------
__device__ __forceinline__ unsigned long long pack2(float a, float b) {
    unsigned long long r;
    asm("mov.b64 %0, {%1, %2};" : "=l"(r) : "f"(a), "f"(b));
    return r;
}
__device__ __forceinline__ void unpack2(unsigned long long v, float& a, float& b) {
    asm("mov.b64 {%0, %1}, %2;" : "=f"(a), "=f"(b) : "l"(v));
}
__device__ __forceinline__ unsigned long long ffma2(
    unsigned long long a, unsigned long long b, unsigned long long c) {
    unsigned long long d;
    asm("fma.rn.f32x2 %0, %1, %2, %3;" : "=l"(d) : "l"(a), "l"(b), "l"(c));
    return d;
}
__device__ __forceinline__ unsigned long long lds_b64(unsigned addr) {
    unsigned long long v;
    asm("ld.shared.b64 %0, [%1];" : "=l"(v) : "r"(addr));
    return v;
}

// ---------------------------------------------------------------------------
// Kernel 0: detect index dtype (int64 vs int32) once.
// ---------------------------------------------------------------------------
__global__ void detect_kernel(const void* __restrict__ neg_p)
{
    const long long* p = (const long long*)neg_p;
    int ok = 1;
    #pragma unroll 1
    for (int i = 0; i < 64; i++) {
        long long v = p[i];
        if (v < 0 || v >= NNODE) { ok = 0; break; }
    }
    g_is64 = ok;
}

// ---------------------------------------------------------------------------
// Kernel 1: gather + 2-layer MLP + l2norm, f32x2 packed across K.
//   Each warp: 8 rows; each lane: cols {lane, lane+32, lane+64, lane+96}.
//   Accumulator f32x2 = (even-k partial, odd-k partial); halves added at end.
//   W staged TRANSPOSED in SMEM: Wt[n][k], stride WT_STRIDE floats, so the
//   (w[k],w[k+1]) operand is one natural b64 load. X tile row-major, so the
//   (x[k],x[k+1]) operand is one natural b64 broadcast. Zero pack movs.
// ---------------------------------------------------------------------------
__global__ void __launch_bounds__(256, 2) proj_kernel(
    const float* __restrict__ emb_p, const float* __restrict__ emb_c,
    const float* __restrict__ W1, const float* __restrict__ b1,
    const float* __restrict__ W2, const float* __restrict__ b2,
    const void* __restrict__ idx_p, const void* __restrict__ idx_c,
    const void* __restrict__ neg_p, const void* __restrict__ neg_c)
{
    extern __shared__ float smem[];
    float* Wt = smem;                        // 128 * 134 floats = 67 KB
    float* Xs = smem + DD * WT_STRIDE;       // 64 * 128 floats  = 32 KB
    __shared__ const float* srcPtr[RPB];

    const int tid = threadIdx.x;
    const int is64 = g_is64;

    // --- decode the 64 source-row pointers ---------------------------------
    if (tid < RPB) {
        int job = blockIdx.x * RPB + tid;
        const float* src;
        if (job < N_ANCHOR) {
            int t = job / 1600, rem = job % 1600;
            int vi = rem / 800;
            int li = (rem / 400) & 1;
            int kk = (rem / 100) & 3;
            int s  = rem % 100;
            const void* ib = t ? idx_c : idx_p;
            int off = (vi * 2 + li) * SS + s;
            int id = is64 ? (int)((const long long*)ib)[off]
                          : ((const int*)ib)[off];
            int vj = (kk & 1)  ? 1 - vi : vi;
            int lj = (kk >= 2) ? 1 - li : li;
            const float* emb = t ? emb_c : emb_p;
            src = emb + ((size_t)(vj * 2 + lj) * NNODE + id) * DD;
        } else {
            int j2 = job - N_ANCHOR;
            int t = j2 / 20000, rem = j2 % 20000;
            int vi = rem / 10000;
            int li = (rem / 5000) & 1;
            int s  = (rem % 5000) / NNEGC;
            int n  = rem % NNEGC;
            const void* nb = t ? neg_c : neg_p;
            int off = ((vi * 2 + li) * SS + s) * NNEGC + n;
            int id = is64 ? (int)((const long long*)nb)[off]
                          : ((const int*)nb)[off];
            const float* emb = t ? emb_p : emb_c;   // OTHER type
            src = emb + ((size_t)(vi * 2 + li) * NNODE + id) * DD;
        }
        srcPtr[tid] = src;
    }
    __syncthreads();

    float4* Xs4 = (float4*)Xs;

    // --- gather X (64 rows x 32 float4); stage W1 transposed ----------------
    for (int i = tid; i < RPB * 32; i += 256)
        Xs4[i] = ((const float4*)srcPtr[i >> 5])[i & 31];
    for (int i = tid; i < DD * DD; i += 256) {
        int k = i >> 7, n = i & 127;
        Wt[n * WT_STRIDE + k] = W1[i];
    }
    __syncthreads();

    const int warp = tid >> 5, lane = tid & 31;
    const int r0 = warp * 8;          // each warp owns rows r0..r0+7

    const unsigned wt_smem = (unsigned)__cvta_generic_to_shared(Wt);
    const unsigned x_base  = (unsigned)__cvta_generic_to_shared(Xs)
                           + (unsigned)r0 * (DD * 4u);
    // per-lane column bases into Wt (cols n = lane + 32c)
    unsigned wbase[4];
    #pragma unroll
    for (int c = 0; c < 4; c++)
        wbase[c] = wt_smem + (unsigned)(lane + 32 * c) * (WT_STRIDE * 4u);

    unsigned long long acc[8][4];     // (even-k partial, odd-k partial)

    // ---------------- Layer 1: H = relu(X @ W1 + b1) -----------------------
    #pragma unroll
    for (int c = 0; c < 4; c++) {
        unsigned long long bi = pack2(b1[lane + 32 * c], 0.0f);
        #pragma unroll
        for (int r = 0; r < 8; r++) acc[r][c] = bi;
    }
    #pragma unroll 4
    for (int kp = 0; kp < DD / 2; kp++) {
        unsigned koff = (unsigned)kp * 8u;
        unsigned long long w0 = lds_b64(wbase[0] + koff);
        unsigned long long w1v = lds_b64(wbase[1] + koff);
        unsigned long long w2v = lds_b64(wbase[2] + koff);
        unsigned long long w3 = lds_b64(wbase[3] + koff);
        #pragma unroll
        for (int r = 0; r < 8; r++) {
            unsigned long long xx = lds_b64(x_base + (unsigned)r * (DD * 4u) + koff);
            acc[r][0] = ffma2(xx, w0, acc[r][0]);
            acc[r][1] = ffma2(xx, w1v, acc[r][1]);
            acc[r][2] = ffma2(xx, w2v, acc[r][2]);
            acc[r][3] = ffma2(xx, w3, acc[r][3]);
        }
    }
    // combine halves + relu, write H back to warp-private Xs rows (scalar STS,
    // lanes consecutive -> conflict-free)
    #pragma unroll
    for (int r = 0; r < 8; r++) {
        #pragma unroll
        for (int c = 0; c < 4; c++) {
            float lo, hi; unpack2(acc[r][c], lo, hi);
            Xs[(r0 + r) * DD + lane + 32 * c] = fmaxf(lo + hi, 0.f);
        }
    }
    __syncthreads();                      // all warps done reading W1
    for (int i = tid; i < DD * DD; i += 256) {
        int k = i >> 7, n = i & 127;
        Wt[n * WT_STRIDE + k] = W2[i];
    }
    __syncthreads();

    // ---------------- Layer 2: Y = H @ W2 + b2 -----------------------------
    #pragma unroll
    for (int c = 0; c < 4; c++) {
        unsigned long long bi = pack2(b2[lane + 32 * c], 0.0f);
        #pragma unroll
        for (int r = 0; r < 8; r++) acc[r][c] = bi;
    }
    #pragma unroll 4
    for (int kp = 0; kp < DD / 2; kp++) {
        unsigned koff = (unsigned)kp * 8u;
        unsigned long long w0 = lds_b64(wbase[0] + koff);
        unsigned long long w1v = lds_b64(wbase[1] + koff);
        unsigned long long w2v = lds_b64(wbase[2] + koff);
        unsigned long long w3 = lds_b64(wbase[3] + koff);
        #pragma unroll
        for (int r = 0; r < 8; r++) {
            unsigned long long xx = lds_b64(x_base + (unsigned)r * (DD * 4u) + koff);
            acc[r][0] = ffma2(xx, w0, acc[r][0]);
            acc[r][1] = ffma2(xx, w1v, acc[r][1]);
            acc[r][2] = ffma2(xx, w2v, acc[r][2]);
            acc[r][3] = ffma2(xx, w3, acc[r][3]);
        }
    }

    // ---------------- l2 normalize + store ---------------------------------
    float y[8][4];
    float ssq[8];
    #pragma unroll
    for (int r = 0; r < 8; r++) {
        float s = 0.f;
        #pragma unroll
        for (int c = 0; c < 4; c++) {
            float lo, hi; unpack2(acc[r][c], lo, hi);
            y[r][c] = lo + hi;
            s += y[r][c] * y[r][c];
        }
        ssq[r] = s;
    }
    #pragma unroll
    for (int off = 16; off > 0; off >>= 1) {
        #pragma unroll
        for (int r = 0; r < 8; r++)
            ssq[r] += __shfl_xor_sync(0xffffffffu, ssq[r], off);
    }
    size_t rowbase = (size_t)blockIdx.x * RPB + r0;
    #pragma unroll
    for (int r = 0; r < 8; r++) {
        float inv = 1.0f / fmaxf(sqrtf(ssq[r]), 1e-12f);
        float* orow = g_proj + (rowbase + r) * DD;
        #pragma unroll
        for (int c = 0; c < 4; c++)
            orow[lane + 32 * c] = y[r][c] * inv;   // coalesced 128B per c
    }
}

// ---------------------------------------------------------------------------
// Kernel 2: per-anchor-sample InfoNCE term. One block per (type, vi, li, s).
// ---------------------------------------------------------------------------
__global__ void __launch_bounds__(128) loss_kernel()
{
    const int b   = blockIdx.x;              // 0..799
    const int key = b / 100;                 // t*4 + vi*2 + li
    const int s   = b % 100;
    const int tid = threadIdx.x;

    __shared__ float zs[DD];
    __shared__ float red_pos[128];
    __shared__ float red_neg[128];

    const float* zrow = g_proj + ((size_t)(key * 4 + 0) * SS + s) * DD;
    zs[tid] = zrow[tid];
    __syncthreads();

    float pos = 0.f, neg = 0.f;
    for (int v = tid; v < 152; v += 128) {
        const float* vec;
        bool is_pos = false;
        if (v < 3) {                                     // positives kk=1..3
            is_pos = true;
            vec = g_proj + ((size_t)(key * 4 + (v + 1)) * SS + s) * DD;
        } else if (v < 102) {                            // within-type negs
            int s2 = v - 3;
            if (s2 >= s) s2++;                           // skip diagonal
            vec = g_proj + ((size_t)(key * 4) * SS + s2) * DD;
        } else {                                         // cross-type negs
            int n = v - 102;
            vec = g_proj + (size_t)N_ANCHOR * DD
                + (((size_t)key * SS + s) * NNEGC + n) * DD;
        }
        const float4* v4 = (const float4*)vec;
        const float4* z4 = (const float4*)zs;
        float d = 0.f;
        #pragma unroll
        for (int i = 0; i < 32; i++) {
            float4 a = z4[i], c = v4[i];
            d += a.x*c.x + a.y*c.y + a.z*c.z + a.w*c.w;
        }
        float e = expf(d * TEMP_INV);
        if (is_pos) pos += e; else neg += e;
    }
    red_pos[tid] = pos;
    red_neg[tid] = neg;
    __syncthreads();
    #pragma unroll
    for (int off = 64; off > 0; off >>= 1) {
        if (tid < off) {
            red_pos[tid] += red_pos[tid + off];
            red_neg[tid] += red_neg[tid + off];
        }
        __syncthreads();
    }
    if (tid == 0) {
        float p = red_pos[0], n = red_neg[0];
        g_loss[b] = -logf(p / (p + n));
    }
}

// ---------------------------------------------------------------------------
// Kernel 3: deterministic final reduction
// ---------------------------------------------------------------------------
__global__ void __launch_bounds__(256) reduce_kernel(float* __restrict__ out)
{
    __shared__ float red[256];
    int tid = threadIdx.x;
    float a = 0.f;
    for (int i = tid; i < N_SAMPLES; i += 256) a += g_loss[i];
    red[tid] = a;
    __syncthreads();
    #pragma unroll
    for (int off = 128; off > 0; off >>= 1) {
        if (tid < off) red[tid] += red[tid + off];
        __syncthreads();
    }
    if (tid == 0) out[0] = red[0] / (float)N_SAMPLES;
}

// ---------------------------------------------------------------------------
// Launch: inputs in metadata order:
//   0 emb_p, 1 emb_c, 2 W1, 3 b1, 4 W2, 5 b2,
//   6 idx_p, 7 idx_c, 8 neg_idx_p, 9 neg_idx_c
// ---------------------------------------------------------------------------
extern "C" void kernel_launch(void* const* d_in, const int* in_sizes, int n_in,
                              void* d_out, int out_size)
{
    (void)in_sizes; (void)n_in; (void)out_size;

    const float* emb_p = (const float*)d_in[0];
    const float* emb_c = (const float*)d_in[1];
    const float* W1    = (const float*)d_in[2];
    const float* b1    = (const float*)d_in[3];
    const float* W2    = (const float*)d_in[4];
    const float* b2    = (const float*)d_in[5];
    const void*  idx_p = d_in[6];
    const void*  idx_c = d_in[7];
    const void*  neg_p = d_in[8];
    const void*  neg_c = d_in[9];
    float* out = (float*)d_out;

    const int smem_bytes = (DD * WT_STRIDE + RPB * DD) * (int)sizeof(float); // ~99 KB
    static int configured = 0;
    if (!configured) {
        cudaFuncSetAttribute(proj_kernel,
                             cudaFuncAttributeMaxDynamicSharedMemorySize,
                             smem_bytes);
        configured = 1;
    }

    detect_kernel<<<1, 1>>>(neg_p);
    proj_kernel<<<N_ROWS / RPB, 256, smem_bytes>>>(
        emb_p, emb_c, W1, b1, W2, b2, idx_p, idx_c, neg_p, neg_c);
    loss_kernel<<<N_SAMPLES, 128>>>();
    reduce_kernel<<<1, 256>>>(out);
}

// round 5
// speedup vs baseline: 1.5673x; 1.5673x over previous
#include <cuda_runtime.h>
#include <cuda_bf16.h>
#include <math.h>

// ---------------------------------------------------------------------------
// Problem constants (V=2, L=2, NP=NC=120000, D=128, S=100, NNEG=50, TEMP=0.5)
// ---------------------------------------------------------------------------
#define DD      128
#define SS      100
#define NNEGC   50
#define NNODE   120000
#define N_ANCHOR 3200
#define N_ROWS   43200
#define N_TILES  675          // 43200 / 64
#define N_SAMPLES 800
#define TEMP_INV 2.0f
#define KST     136           // padded k-stride (bf16 elems): conflict-free frags
#define WSPL    (128 * KST)   // 17408 elems per (layer,split) matrix
#define WBYTES  (4 * WSPL * 2) // 139264 B : {W1,W2} x {hi,lo}

// Scratch (device globals: no runtime allocation allowed)
__device__ float g_proj[(size_t)N_ROWS * DD];   // ~22.1 MB
__device__ float g_loss[N_SAMPLES];
__device__ int   g_is64;
__device__ int   g_count = 0;
__device__ __nv_bfloat16 g_Wt[4 * WSPL];        // transposed+split weights

// ---------------------------------------------------------------------------
// mma.sync m16n8k16 bf16 (row-major A, col-major B), f32 accumulate
// ---------------------------------------------------------------------------
__device__ __forceinline__ void mma_bf16(float* d, const unsigned* a,
                                         unsigned b0, unsigned b1) {
    asm volatile(
        "mma.sync.aligned.m16n8k16.row.col.f32.bf16.bf16.f32 "
        "{%0,%1,%2,%3}, {%4,%5,%6,%7}, {%8,%9}, {%0,%1,%2,%3};"
        : "+f"(d[0]), "+f"(d[1]), "+f"(d[2]), "+f"(d[3])
        : "r"(a[0]), "r"(a[1]), "r"(a[2]), "r"(a[3]), "r"(b0), "r"(b1));
}

// ---------------------------------------------------------------------------
// Kernel 0: (a) parallel index-dtype detect, (b) build transposed split-bf16 W.
//   g_Wt[(l*2+s)*WSPL + n*KST + k] = split_s( W_l[k*128 + n] )
// ---------------------------------------------------------------------------
__global__ void prep_kernel(const float* __restrict__ W1,
                            const float* __restrict__ W2,
                            const void* __restrict__ neg_p)
{
    if (blockIdx.x == 0 && threadIdx.x < 32) {
        const long long* p = (const long long*)neg_p;
        long long v = p[threadIdx.x];
        unsigned bad = __ballot_sync(0xffffffffu, v < 0 || v >= NNODE);
        if (threadIdx.x == 0) g_is64 = (bad == 0);
    }
    for (int i = blockIdx.x * 256 + threadIdx.x; i < 2 * DD * DD;
         i += gridDim.x * 256) {
        int l = i >> 14, rem = i & 16383;
        int k = rem >> 7, n = rem & 127;
        float w = (l ? W2 : W1)[rem];
        __nv_bfloat16 hi = __float2bfloat16(w);
        __nv_bfloat16 lo = __float2bfloat16(w - __bfloat162float(hi));
        g_Wt[(l * 2 + 0) * WSPL + n * KST + k] = hi;
        g_Wt[(l * 2 + 1) * WSPL + n * KST + k] = lo;
    }
}

// ---------------------------------------------------------------------------
// Kernel 1: gather + 2-layer MLP + l2norm on tensor cores (3xBF16 split).
//   grid=148 persistent-ish; each block stages all W once, loops 64-row tiles.
//   Warp w: row-group rg=w>>1 (rows rg*16..+15), col-half ch=w&1 (cols ch*64..).
// ---------------------------------------------------------------------------
__global__ void __launch_bounds__(256, 1) proj_kernel(
    const float* __restrict__ emb_p, const float* __restrict__ emb_c,
    const float* __restrict__ b1,    const float* __restrict__ b2,
    const void* __restrict__ idx_p,  const void* __restrict__ idx_c,
    const void* __restrict__ neg_p,  const void* __restrict__ neg_c)
{
    extern __shared__ unsigned char sm[];
    __nv_bfloat16* Wsm = (__nv_bfloat16*)sm;                       // 139264 B
    __nv_bfloat16* Xhi = (__nv_bfloat16*)(sm + WBYTES);            // 64*KST*2
    __nv_bfloat16* Xlo = (__nv_bfloat16*)(sm + WBYTES + 64 * KST * 2);
    float* b1s   = (float*)(sm + WBYTES + 2 * 64 * KST * 2);
    float* b2s   = b1s + DD;
    float* ssq_s = b2s + DD;                                       // [2][64]
    __shared__ const float* srcPtr[64];

    const int tid = threadIdx.x;

    // --- stage all weights once (vectorized flat copy) + biases ------------
    {
        const uint4* src = (const uint4*)g_Wt;
        uint4* dst = (uint4*)Wsm;
        for (int i = tid; i < WBYTES / 16; i += 256) dst[i] = src[i];
        if (tid < DD) { b1s[tid] = b1[tid]; b2s[tid] = b2[tid]; }
    }
    const int is64 = g_is64;

    const int lane = tid & 31, warp = tid >> 5;
    const int qr = lane >> 2, qc = lane & 3;
    const int rg = warp >> 1, ch = warp & 1;
    const int R0 = rg * 16, C0 = ch * 64;

    for (int tile = blockIdx.x; tile < N_TILES; tile += gridDim.x) {
        __syncthreads();   // protect Xhi/Xlo/ssq_s from previous iteration

        // --- decode 64 source-row pointers ---------------------------------
        if (tid < 64) {
            int job = tile * 64 + tid;
            const float* src;
            if (job < N_ANCHOR) {
                int t = job / 1600, rem = job % 1600;
                int vi = rem / 800;
                int li = (rem / 400) & 1;
                int kk = (rem / 100) & 3;
                int s  = rem % 100;
                const void* ib = t ? idx_c : idx_p;
                int off = (vi * 2 + li) * SS + s;
                int id = is64 ? (int)((const long long*)ib)[off]
                              : ((const int*)ib)[off];
                int vj = (kk & 1)  ? 1 - vi : vi;
                int lj = (kk >= 2) ? 1 - li : li;
                const float* emb = t ? emb_c : emb_p;
                src = emb + ((size_t)(vj * 2 + lj) * NNODE + id) * DD;
            } else {
                int j2 = job - N_ANCHOR;
                int t = j2 / 20000, rem = j2 % 20000;
                int vi = rem / 10000;
                int li = (rem / 5000) & 1;
                int s  = (rem % 5000) / NNEGC;
                int n  = rem % NNEGC;
                const void* nb = t ? neg_c : neg_p;
                int off = ((vi * 2 + li) * SS + s) * NNEGC + n;
                int id = is64 ? (int)((const long long*)nb)[off]
                              : ((const int*)nb)[off];
                const float* emb = t ? emb_p : emb_c;   // OTHER type
                src = emb + ((size_t)(vi * 2 + li) * NNODE + id) * DD;
            }
            srcPtr[tid] = src;
        }
        __syncthreads();

        // --- gather + split X into bf16 hi/lo ------------------------------
        for (int i = tid; i < 64 * 32; i += 256) {
            int row = i >> 5, q = i & 31;
            float4 v = ((const float4*)srcPtr[row])[q];
            int base = row * KST + q * 4;
            float xv[4] = {v.x, v.y, v.z, v.w};
            #pragma unroll
            for (int j = 0; j < 4; j++) {
                __nv_bfloat16 h = __float2bfloat16(xv[j]);
                Xhi[base + j] = h;
                Xlo[base + j] = __float2bfloat16(xv[j] - __bfloat162float(h));
            }
        }
        __syncthreads();

        float acc[8][4];

        // ================= Layer 1: H = relu(X @ W1 + b1) ==================
        #pragma unroll
        for (int nt = 0; nt < 8; nt++)
            #pragma unroll
            for (int j = 0; j < 4; j++) acc[nt][j] = 0.f;
        {
            const __nv_bfloat16* Wh = Wsm;          // layer 0 hi
            const __nv_bfloat16* Wl = Wsm + WSPL;   // layer 0 lo
            #pragma unroll
            for (int kt = 0; kt < 8; kt++) {
                int k0 = kt * 16 + qc * 2;
                const __nv_bfloat16* xh = Xhi + (R0 + qr) * KST + k0;
                const __nv_bfloat16* xl = Xlo + (R0 + qr) * KST + k0;
                unsigned ah[4], al[4];
                ah[0] = *(const unsigned*)(xh);
                ah[1] = *(const unsigned*)(xh + 8 * KST);
                ah[2] = *(const unsigned*)(xh + 8);
                ah[3] = *(const unsigned*)(xh + 8 * KST + 8);
                al[0] = *(const unsigned*)(xl);
                al[1] = *(const unsigned*)(xl + 8 * KST);
                al[2] = *(const unsigned*)(xl + 8);
                al[3] = *(const unsigned*)(xl + 8 * KST + 8);
                #pragma unroll
                for (int nt = 0; nt < 8; nt++) {
                    int wrow = (C0 + nt * 8 + qr) * KST + k0;
                    unsigned bh0 = *(const unsigned*)(Wh + wrow);
                    unsigned bh1 = *(const unsigned*)(Wh + wrow + 8);
                    unsigned bl0 = *(const unsigned*)(Wl + wrow);
                    unsigned bl1 = *(const unsigned*)(Wl + wrow + 8);
                    mma_bf16(acc[nt], ah, bh0, bh1);
                    mma_bf16(acc[nt], ah, bl0, bl1);
                    mma_bf16(acc[nt], al, bh0, bh1);
                }
            }
        }
        __syncthreads();          // everyone done READING X before overwrite

        // bias + relu + split, write H into Xhi/Xlo
        #pragma unroll
        for (int nt = 0; nt < 8; nt++) {
            int col = C0 + nt * 8 + qc * 2;
            float h0 = fmaxf(acc[nt][0] + b1s[col],     0.f);
            float h1 = fmaxf(acc[nt][1] + b1s[col + 1], 0.f);
            float h2 = fmaxf(acc[nt][2] + b1s[col],     0.f);
            float h3 = fmaxf(acc[nt][3] + b1s[col + 1], 0.f);
            int alo = (R0 + qr) * KST + col;
            int ahi = (R0 + qr + 8) * KST + col;
            __nv_bfloat16 t0 = __float2bfloat16(h0);
            __nv_bfloat16 t1 = __float2bfloat16(h1);
            __nv_bfloat16 t2 = __float2bfloat16(h2);
            __nv_bfloat16 t3 = __float2bfloat16(h3);
            Xhi[alo]     = t0; Xlo[alo]     = __float2bfloat16(h0 - __bfloat162float(t0));
            Xhi[alo + 1] = t1; Xlo[alo + 1] = __float2bfloat16(h1 - __bfloat162float(t1));
            Xhi[ahi]     = t2; Xlo[ahi]     = __float2bfloat16(h2 - __bfloat162float(t2));
            Xhi[ahi + 1] = t3; Xlo[ahi + 1] = __float2bfloat16(h3 - __bfloat162float(t3));
        }
        __syncthreads();

        // ================= Layer 2: Y = H @ W2 + b2 ========================
        #pragma unroll
        for (int nt = 0; nt < 8; nt++)
            #pragma unroll
            for (int j = 0; j < 4; j++) acc[nt][j] = 0.f;
        {
            const __nv_bfloat16* Wh = Wsm + 2 * WSPL;   // layer 1 hi
            const __nv_bfloat16* Wl = Wsm + 3 * WSPL;   // layer 1 lo
            #pragma unroll
            for (int kt = 0; kt < 8; kt++) {
                int k0 = kt * 16 + qc * 2;
                const __nv_bfloat16* xh = Xhi + (R0 + qr) * KST + k0;
                const __nv_bfloat16* xl = Xlo + (R0 + qr) * KST + k0;
                unsigned ah[4], al[4];
                ah[0] = *(const unsigned*)(xh);
                ah[1] = *(const unsigned*)(xh + 8 * KST);
                ah[2] = *(const unsigned*)(xh + 8);
                ah[3] = *(const unsigned*)(xh + 8 * KST + 8);
                al[0] = *(const unsigned*)(xl);
                al[1] = *(const unsigned*)(xl + 8 * KST);
                al[2] = *(const unsigned*)(xl + 8);
                al[3] = *(const unsigned*)(xl + 8 * KST + 8);
                #pragma unroll
                for (int nt = 0; nt < 8; nt++) {
                    int wrow = (C0 + nt * 8 + qr) * KST + k0;
                    unsigned bh0 = *(const unsigned*)(Wh + wrow);
                    unsigned bh1 = *(const unsigned*)(Wh + wrow + 8);
                    unsigned bl0 = *(const unsigned*)(Wl + wrow);
                    unsigned bl1 = *(const unsigned*)(Wl + wrow + 8);
                    mma_bf16(acc[nt], ah, bh0, bh1);
                    mma_bf16(acc[nt], ah, bl0, bl1);
                    mma_bf16(acc[nt], al, bh0, bh1);
                }
            }
        }

        // ================= epilogue: bias, l2norm, store ===================
        float sl = 0.f, sh = 0.f;
        #pragma unroll
        for (int nt = 0; nt < 8; nt++) {
            int col = C0 + nt * 8 + qc * 2;
            acc[nt][0] += b2s[col];     acc[nt][1] += b2s[col + 1];
            acc[nt][2] += b2s[col];     acc[nt][3] += b2s[col + 1];
            sl += acc[nt][0] * acc[nt][0] + acc[nt][1] * acc[nt][1];
            sh += acc[nt][2] * acc[nt][2] + acc[nt][3] * acc[nt][3];
        }
        sl += __shfl_xor_sync(0xffffffffu, sl, 1);
        sl += __shfl_xor_sync(0xffffffffu, sl, 2);
        sh += __shfl_xor_sync(0xffffffffu, sh, 1);
        sh += __shfl_xor_sync(0xffffffffu, sh, 2);
        if (qc == 0) {
            ssq_s[ch * 64 + R0 + qr]     = sl;
            ssq_s[ch * 64 + R0 + qr + 8] = sh;
        }
        __syncthreads();
        float tlo = ssq_s[R0 + qr]     + ssq_s[64 + R0 + qr];
        float thi = ssq_s[R0 + qr + 8] + ssq_s[64 + R0 + qr + 8];
        float il = 1.0f / fmaxf(sqrtf(tlo), 1e-12f);
        float ih = 1.0f / fmaxf(sqrtf(thi), 1e-12f);
        float* outlo = g_proj + ((size_t)tile * 64 + R0 + qr) * DD;
        float* outhi = g_proj + ((size_t)tile * 64 + R0 + qr + 8) * DD;
        #pragma unroll
        for (int nt = 0; nt < 8; nt++) {
            int col = C0 + nt * 8 + qc * 2;
            float2 v0 = make_float2(acc[nt][0] * il, acc[nt][1] * il);
            float2 v1 = make_float2(acc[nt][2] * ih, acc[nt][3] * ih);
            *(float2*)(outlo + col) = v0;
            *(float2*)(outhi + col) = v1;
        }
    }
}

// ---------------------------------------------------------------------------
// Kernel 2: per-anchor InfoNCE + fused final reduction (last block).
// ---------------------------------------------------------------------------
__global__ void __launch_bounds__(128) loss_kernel(float* __restrict__ out)
{
    const int b   = blockIdx.x;              // 0..799
    const int key = b / 100;                 // t*4 + vi*2 + li
    const int s   = b % 100;
    const int tid = threadIdx.x;

    __shared__ float zs[DD];
    __shared__ float red_pos[128];
    __shared__ float red_neg[128];
    __shared__ int amLast;

    const float* zrow = g_proj + ((size_t)(key * 4 + 0) * SS + s) * DD;
    zs[tid] = zrow[tid];
    __syncthreads();

    float pos = 0.f, neg = 0.f;
    for (int v = tid; v < 152; v += 128) {
        const float* vec;
        bool is_pos = false;
        if (v < 3) {                                     // positives kk=1..3
            is_pos = true;
            vec = g_proj + ((size_t)(key * 4 + (v + 1)) * SS + s) * DD;
        } else if (v < 102) {                            // within-type negs
            int s2 = v - 3;
            if (s2 >= s) s2++;                           // skip diagonal
            vec = g_proj + ((size_t)(key * 4) * SS + s2) * DD;
        } else {                                         // cross-type negs
            int n = v - 102;
            vec = g_proj + (size_t)N_ANCHOR * DD
                + (((size_t)key * SS + s) * NNEGC + n) * DD;
        }
        const float4* v4 = (const float4*)vec;
        const float4* z4 = (const float4*)zs;
        float d = 0.f;
        #pragma unroll
        for (int i = 0; i < 32; i++) {
            float4 a = z4[i], c = v4[i];
            d += a.x*c.x + a.y*c.y + a.z*c.z + a.w*c.w;
        }
        float e = expf(d * TEMP_INV);
        if (is_pos) pos += e; else neg += e;
    }
    red_pos[tid] = pos;
    red_neg[tid] = neg;
    __syncthreads();
    #pragma unroll
    for (int off = 64; off > 0; off >>= 1) {
        if (tid < off) {
            red_pos[tid] += red_pos[tid + off];
            red_neg[tid] += red_neg[tid + off];
        }
        __syncthreads();
    }
    if (tid == 0) {
        float p = red_pos[0], n = red_neg[0];
        g_loss[b] = -logf(p / (p + n));
        __threadfence();
        int c = atomicAdd(&g_count, 1);
        amLast = (c == N_SAMPLES - 1);
    }
    __syncthreads();
    if (amLast) {
        __threadfence();
        float a = 0.f;
        for (int i = tid; i < N_SAMPLES; i += 128) a += g_loss[i];
        red_pos[tid] = a;
        __syncthreads();
        #pragma unroll
        for (int off = 64; off > 0; off >>= 1) {
            if (tid < off) red_pos[tid] += red_pos[tid + off];
            __syncthreads();
        }
        if (tid == 0) {
            out[0] = red_pos[0] / (float)N_SAMPLES;
            g_count = 0;                 // reset for next graph replay
        }
    }
}

// ---------------------------------------------------------------------------
// Launch: inputs in metadata order:
//   0 emb_p, 1 emb_c, 2 W1, 3 b1, 4 W2, 5 b2,
//   6 idx_p, 7 idx_c, 8 neg_idx_p, 9 neg_idx_c
// ---------------------------------------------------------------------------
extern "C" void kernel_launch(void* const* d_in, const int* in_sizes, int n_in,
                              void* d_out, int out_size)
{
    (void)in_sizes; (void)n_in; (void)out_size;

    const float* emb_p = (const float*)d_in[0];
    const float* emb_c = (const float*)d_in[1];
    const float* W1    = (const float*)d_in[2];
    const float* b1    = (const float*)d_in[3];
    const float* W2    = (const float*)d_in[4];
    const float* b2    = (const float*)d_in[5];
    const void*  idx_p = d_in[6];
    const void*  idx_c = d_in[7];
    const void*  neg_p = d_in[8];
    const void*  neg_c = d_in[9];
    float* out = (float*)d_out;

    const int smem_bytes = WBYTES + 2 * 64 * KST * 2      // W + Xhi + Xlo
                         + 2 * DD * 4 + 2 * 64 * 4;       // biases + ssq
    static int configured = 0;
    if (!configured) {
        cudaFuncSetAttribute(proj_kernel,
                             cudaFuncAttributeMaxDynamicSharedMemorySize,
                             smem_bytes);
        configured = 1;
    }

    prep_kernel<<<64, 256>>>(W1, W2, neg_p);
    proj_kernel<<<148, 256, smem_bytes>>>(
        emb_p, emb_c, b1, b2, idx_p, idx_c, neg_p, neg_c);
    loss_kernel<<<N_SAMPLES, 128>>>(out);
}